// round 1
// baseline (speedup 1.0000x reference)
#include <cuda_runtime.h>
#include <cuda_bf16.h>

#define MW_F 1280.0f
#define MH_F 768.0f
#define HH 384
#define WW 640
#define HW (HH*WW)
#define BS 4
#define NBOX 64
#define NB (BS*NBOX)
#define SCALE_F 80.0f
#define MAXRC 104
#define MAXCELLS (MAXRC*MAXRC)

// Per-box scratch (phase1 -> phase2)
__device__ float g_thr[NB], g_cx[NB], g_cy[NB], g_bw[NB], g_bh[NB], g_score[NB], g_lam[NB];
__device__ int   g_bx[NB], g_by[NB], g_cls[NB];

struct PGeom { float mnx, mxx, mny, mxy, pw, ph; };

// Pinned-rounding pred-box geometry (identical in both phases -> bit-identical IoU)
__device__ __forceinline__ PGeom pred_geom(float p0, float p1, float p2, float p3,
                                           float rx, float ry) {
    float x1 = __fadd_rn(__fmul_rn(p0, SCALE_F), rx);
    float y1 = __fadd_rn(__fmul_rn(p1, SCALE_F), ry);
    float x2 = __fadd_rn(__fmul_rn(p2, SCALE_F), rx);
    float y2 = __fadd_rn(__fmul_rn(p3, SCALE_F), ry);
    float w  = __fsub_rn(x2, x1);
    float h  = __fsub_rn(y2, y1);
    float cx = __fadd_rn(x1, __fmul_rn(w, 0.5f));
    float cy = __fadd_rn(y1, __fmul_rn(h, 0.5f));
    PGeom g;
    g.mnx = __fsub_rn(cx, __fmul_rn(w, 0.5f));
    g.mxx = __fadd_rn(cx, __fmul_rn(w, 0.5f));
    g.mny = __fsub_rn(cy, __fmul_rn(h, 0.5f));
    g.mxy = __fadd_rn(cy, __fmul_rn(h, 0.5f));
    g.pw = w; g.ph = h;
    return g;
}

__device__ __forceinline__ float iou_fn(const PGeom& g, float cx, float cy,
                                        float bw, float bh) {
    float gmnx = __fsub_rn(cx, __fmul_rn(bw, 0.5f));
    float gmxx = __fadd_rn(cx, __fmul_rn(bw, 0.5f));
    float gmny = __fsub_rn(cy, __fmul_rn(bh, 0.5f));
    float gmxy = __fadd_rn(cy, __fmul_rn(bh, 0.5f));
    float iw = fmaxf(__fsub_rn(fminf(g.mxx, gmxx), fmaxf(g.mnx, gmnx)), 0.0f);
    float ih = fmaxf(__fsub_rn(fminf(g.mxy, gmxy), fmaxf(g.mny, gmny)), 0.0f);
    float inter = __fmul_rn(iw, ih);
    float uni = __fsub_rn(__fadd_rn(__fmul_rn(g.pw, g.ph), __fmul_rn(bw, bh)), inter);
    return __fdiv_rn(inter, fmaxf(uni, 1e-6f));
}

// ---------------- Phase 1: per-box region IoU + exact rank-dk threshold ----------------
__global__ __launch_bounds__(256) void phase1_kernel(
    const float* __restrict__ pred,    // [BS,4,H,W]
    const float* __restrict__ bboxes,  // [BS,NBOX,6]
    const int*   __restrict__ dmode)
{
    __shared__ float vals[MAXCELLS];
    __shared__ unsigned hist[256];
    __shared__ float redf[256];
    __shared__ int   redi[256];
    __shared__ float s_thr_sh;
    __shared__ int   s_dk, s_P;
    __shared__ unsigned s_prefix;
    __shared__ int   s_want;

    const int bn = blockIdx.x;
    const int b = bn / NBOX;
    const int tid = threadIdx.x;

    const float* bx = bboxes + bn * 6;
    float x1 = bx[0], y1 = bx[1], x2 = bx[2], y2 = bx[3], clsf = bx[4], diff = bx[5];
    float bw = __fsub_rn(x2, x1);
    float bh = __fsub_rn(y2, y1);
    float cx = __fadd_rn(x1, __fmul_rn(bw, 0.5f));
    float cy = __fadd_rn(y1, __fmul_rn(bh, 0.5f));
    bool valid = (__fmul_rn(bw, bh) != 0.0f);

    // region bounds (match reference op order: x*W/MODEL_W)
    float mnw = floorf(fmaxf(__fsub_rn(__fdiv_rn(__fmul_rn(x1, (float)WW), MW_F), 0.5f), 0.0f));
    float mnh = floorf(fmaxf(__fsub_rn(__fdiv_rn(__fmul_rn(y1, (float)HH), MH_F), 0.5f), 0.0f));
    float mxw = ceilf (fminf(__fsub_rn(__fdiv_rn(__fmul_rn(x2, (float)WW), MW_F), 0.5f), (float)(WW - 1)));
    float mxh = ceilf (fminf(__fsub_rn(__fdiv_rn(__fmul_rn(y2, (float)HH), MH_F), 0.5f), (float)(HH - 1)));
    int ix0 = (int)mnw, ix1 = (int)mxw, iy0 = (int)mnh, iy1 = (int)mxh;
    bool empty = (!valid) || (ix1 < ix0) || (iy1 < iy0);
    int rw = empty ? 0 : (ix1 - ix0 + 1);
    int rh = empty ? 0 : (iy1 - iy0 + 1);
    int cnt = rw * rh;
    if (cnt > MAXCELLS) cnt = MAXCELLS;  // safety, should not trigger for these inputs

    // compute IoUs over region cells
    float psum = 0.0f;
    int pcount = 0;
    for (int c = tid; c < cnt; c += 256) {
        int ri = c / rw;
        int rj = c - ri * rw;
        int i = iy0 + ri, j = ix0 + rj;
        const float* pb = pred + ((long)b * 4) * HW + (long)i * WW + j;
        float p0 = pb[0 * HW], p1 = pb[1 * HW], p2 = pb[2 * HW], p3 = pb[3 * HW];
        float rx = __fmul_rn(__fadd_rn((float)j, 0.5f), 2.0f);
        float ry = __fmul_rn(__fadd_rn((float)i, 0.5f), 2.0f);
        PGeom g = pred_geom(p0, p1, p2, p3, rx, ry);
        float iou = iou_fn(g, cx, cy, bw, bh);
        vals[c] = iou;
        psum += iou;
        if (iou > 0.0f) pcount++;
    }

    // block reduce sum + positive count
    redf[tid] = psum; redi[tid] = pcount;
    __syncthreads();
    for (int s = 128; s > 0; s >>= 1) {
        if (tid < s) { redf[tid] += redf[tid + s]; redi[tid] += redi[tid + s]; }
        __syncthreads();
    }
    if (tid == 0) {
        float total = redf[0];
        float dkf = ceilf(fmaxf(total, 1.0f));
        if (!(dkf < (float)(HW - 1))) dkf = (float)(HW - 1);  // also catches NaN/inf
        s_dk = (int)dkf;
        s_P = redi[0];
        s_prefix = 0u;
        s_want = (int)dkf;
        s_thr_sh = 0.0f;
    }
    __syncthreads();

    int dk = s_dk;
    int P = s_P;

    if (dk < P) {
        // MSB radix select of rank-dk (0-indexed desc) among positive vals
        for (int shift = 24; shift >= 0; shift -= 8) {
            hist[tid] = 0u;
            __syncthreads();
            unsigned umask = (shift == 24) ? 0u : (0xFFFFFFFFu << (shift + 8));
            unsigned pref = s_prefix;
            for (int c = tid; c < cnt; c += 256) {
                float v = vals[c];
                if (v > 0.0f) {
                    unsigned u = __float_as_uint(v);
                    if ((u & umask) == pref)
                        atomicAdd(&hist[(u >> shift) & 255u], 1u);
                }
            }
            __syncthreads();
            if (tid == 0) {
                int want = s_want;
                int bbin = 255;
                for (; bbin > 0; bbin--) {
                    int h = (int)hist[bbin];
                    if (want < h) break;
                    want -= h;
                }
                s_prefix = pref | ((unsigned)bbin << shift);
                s_want = want;
            }
            __syncthreads();
        }
        if (tid == 0) s_thr_sh = __uint_as_float(s_prefix);
        __syncthreads();
    }

    if (tid == 0) {
        g_thr[bn] = s_thr_sh;
        g_cx[bn] = cx; g_cy[bn] = cy; g_bw[bn] = bw; g_bh[bn] = bh;
        int dm = *dmode;
        g_score[bn] = dm ? ((diff >= 0.625f) ? 1.0f : 0.0f) : 1.0f;
        g_lam[bn] = 1.0f / sqrtf((float)dk);
        g_cls[bn] = (int)clsf + 1;
        if (empty) { g_bx[bn] = 0xFFFF; g_by[bn] = 0xFFFF; }
        else       { g_bx[bn] = ix0 | (ix1 << 16); g_by[bn] = iy0 | (iy1 << 16); }
    }
}

// ---------------- Phase 2: per-pixel argmax/tie across boxes + outputs ----------------
__global__ __launch_bounds__(256) void phase2_kernel(
    const float* __restrict__ pred,  // [BS,4,H,W]
    float* __restrict__ out)         // cls [BS,H,W,3] then pts [BS,H,W,6]
{
    __shared__ unsigned s_mask[2];
    __shared__ int   s_ncand;
    __shared__ int   s_bxp[NBOX], s_byp[NBOX], s_clsid[NBOX];
    __shared__ float s_thr[NBOX], s_cx[NBOX], s_cy[NBOX], s_bw[NBOX], s_bh[NBOX];
    __shared__ float s_sc[NBOX], s_lm[NBOX];

    const int b = blockIdx.z;
    const int j0 = blockIdx.x * 64;
    const int i0 = blockIdx.y * 4;
    const int tid = threadIdx.x;

    // order-preserving compaction of boxes overlapping this 64x4 tile
    bool f = false;
    int bxp = 0, byp = 0;
    if (tid < NBOX) {
        int idx = b * NBOX + tid;
        bxp = g_bx[idx]; byp = g_by[idx];
        int x0 = bxp & 0xFFFF, x1 = bxp >> 16;
        int y0 = byp & 0xFFFF, y1 = byp >> 16;
        f = (x0 <= j0 + 63) && (x1 >= j0) && (y0 <= i0 + 3) && (y1 >= i0);
    }
    unsigned m = __ballot_sync(0xFFFFFFFFu, f);
    if (tid < NBOX && (tid & 31) == 0) s_mask[tid >> 5] = m;
    __syncthreads();
    int base0 = __popc(s_mask[0]);
    if (tid == 0) s_ncand = base0 + __popc(s_mask[1]);
    if (f) {
        int lane = tid & 31;
        int pos = ((tid >> 5) ? base0 : 0) + __popc(m & ((1u << lane) - 1u));
        int idx = b * NBOX + tid;
        s_bxp[pos] = bxp; s_byp[pos] = byp;
        s_thr[pos] = g_thr[idx];
        s_cx[pos] = g_cx[idx]; s_cy[pos] = g_cy[idx];
        s_bw[pos] = g_bw[idx]; s_bh[pos] = g_bh[idx];
        s_sc[pos] = g_score[idx]; s_lm[pos] = g_lam[idx];
        s_clsid[pos] = g_cls[idx];
    }
    __syncthreads();

    const int j = j0 + (tid & 63);
    const int i = i0 + (tid >> 6);
    const int pix = i * WW + j;

    const float* pb = pred + ((long)b * 4) * HW + pix;
    float p0 = pb[0 * HW], p1 = pb[1 * HW], p2 = pb[2 * HW], p3 = pb[3 * HW];
    float rx = __fmul_rn(__fadd_rn((float)j, 0.5f), 2.0f);
    float ry = __fmul_rn(__fadd_rn((float)i, 0.5f), 2.0f);
    PGeom g = pred_geom(p0, p1, p2, p3, rx, ry);

    float best = 0.0f;
    int win = 0;
    int cntmax = 0;
    bool inreg = false;
    const int nc = s_ncand;
    for (int k = 0; k < nc; k++) {
        int bp = s_bxp[k], yp = s_byp[k];
        if (j >= (bp & 0xFFFF) && j <= (bp >> 16) &&
            i >= (yp & 0xFFFF) && i <= (yp >> 16)) {
            inreg = true;
            float iou = iou_fn(g, s_cx[k], s_cy[k], s_bw[k], s_bh[k]);
            float kept = (iou > s_thr[k]) ? iou : 0.0f;
            if (kept > best) { best = kept; win = k; cntmax = 1; }
            else if (kept == best && kept > 0.0f) cntmax++;
        }
    }

    bool assigned = (best > 0.0f);
    float c0, c1, c2;
    if (assigned) {
        if (cntmax > 1) { c0 = c1 = c2 = 0.0f; }
        else {
            int ci = s_clsid[win];
            c0 = (ci == 0) ? 1.0f : 0.0f;
            c1 = (ci == 1) ? 1.0f : 0.0f;
            c2 = (ci == 2) ? 1.0f : 0.0f;
        }
    } else if (inreg) {
        c0 = c1 = c2 = 0.0f;
    } else {
        c0 = 1.0f; c1 = 0.0f; c2 = 0.0f;
    }
    int cidx = (b * HW + pix) * 3;
    out[cidx + 0] = c0; out[cidx + 1] = c1; out[cidx + 2] = c2;

    int pidx = BS * HW * 3 + (b * HW + pix) * 6;
    if (assigned) {
        out[pidx + 0] = s_cx[win];
        out[pidx + 1] = s_cy[win];
        out[pidx + 2] = s_bw[win];
        out[pidx + 3] = s_bh[win];
        out[pidx + 4] = s_sc[win];
        out[pidx + 5] = s_lm[win];
    } else {
        out[pidx + 0] = 1.0f; out[pidx + 1] = 1.0f; out[pidx + 2] = 1.0f;
        out[pidx + 3] = 1.0f; out[pidx + 4] = 1.0f; out[pidx + 5] = 1.0f;
    }
}

extern "C" void kernel_launch(void* const* d_in, const int* in_sizes, int n_in,
                              void* d_out, int out_size) {
    // inputs: [0]=feat (unused), [1]=pred, [2]=bboxes, [3]=difficult_mode (int32)
    const float* pred   = (const float*)d_in[1];
    const float* bboxes = (const float*)d_in[2];
    const int*   dmode  = (const int*)d_in[3];
    float* out = (float*)d_out;

    phase1_kernel<<<NB, 256>>>(pred, bboxes, dmode);
    dim3 g2(WW / 64, HH / 4, BS);
    phase2_kernel<<<g2, 256>>>(pred, out);
}

// round 3
// speedup vs baseline: 1.2577x; 1.2577x over previous
#include <cuda_runtime.h>
#include <cuda_bf16.h>

#define MW_F 1280.0f
#define MH_F 768.0f
#define HH 384
#define WW 640
#define HW (HH*WW)
#define BS 4
#define NBOX 64
#define NB (BS*NBOX)
#define SCALE_F 80.0f
#define MAXRC 104
#define MAXCELLS (MAXRC*MAXRC)

// dynamic smem layout: vals[MAXCELLS] | hist[2048] | scan[256]
#define SMEM1_BYTES (MAXCELLS*4 + 2048*4 + 256*4)

// Per-box scratch (phase1 -> phase2)
__device__ float g_thr[NB], g_cx[NB], g_cy[NB], g_bw[NB], g_bh[NB], g_score[NB], g_lam[NB];
__device__ int   g_bx[NB], g_by[NB], g_cls[NB];

struct PGeom { float mnx, mxx, mny, mxy, pw, ph; };

// Pinned-rounding pred-box geometry (identical in both phases -> bit-identical IoU)
__device__ __forceinline__ PGeom pred_geom(float p0, float p1, float p2, float p3,
                                           float rx, float ry) {
    float x1 = __fadd_rn(__fmul_rn(p0, SCALE_F), rx);
    float y1 = __fadd_rn(__fmul_rn(p1, SCALE_F), ry);
    float x2 = __fadd_rn(__fmul_rn(p2, SCALE_F), rx);
    float y2 = __fadd_rn(__fmul_rn(p3, SCALE_F), ry);
    float w  = __fsub_rn(x2, x1);
    float h  = __fsub_rn(y2, y1);
    float cx = __fadd_rn(x1, __fmul_rn(w, 0.5f));
    float cy = __fadd_rn(y1, __fmul_rn(h, 0.5f));
    PGeom g;
    g.mnx = __fsub_rn(cx, __fmul_rn(w, 0.5f));
    g.mxx = __fadd_rn(cx, __fmul_rn(w, 0.5f));
    g.mny = __fsub_rn(cy, __fmul_rn(h, 0.5f));
    g.mxy = __fadd_rn(cy, __fmul_rn(h, 0.5f));
    g.pw = w; g.ph = h;
    return g;
}

__device__ __forceinline__ float iou_fn(const PGeom& g, float cx, float cy,
                                        float bw, float bh) {
    float gmnx = __fsub_rn(cx, __fmul_rn(bw, 0.5f));
    float gmxx = __fadd_rn(cx, __fmul_rn(bw, 0.5f));
    float gmny = __fsub_rn(cy, __fmul_rn(bh, 0.5f));
    float gmxy = __fadd_rn(cy, __fmul_rn(bh, 0.5f));
    float iw = fmaxf(__fsub_rn(fminf(g.mxx, gmxx), fmaxf(g.mnx, gmnx)), 0.0f);
    float ih = fmaxf(__fsub_rn(fminf(g.mxy, gmxy), fmaxf(g.mny, gmny)), 0.0f);
    float inter = __fmul_rn(iw, ih);
    float uni = __fsub_rn(__fadd_rn(__fmul_rn(g.pw, g.ph), __fmul_rn(bw, bh)), inter);
    return __fdiv_rn(inter, fmaxf(uni, 1e-6f));
}

// Parallel locate: find bin B s.t. suffixsum(bins>B) <= want < suffixsum+hist[B].
// Writes *s_bin / *s_wrem (shared). All 256 threads participate. Ends synced.
__device__ __forceinline__ void locate_bin(const unsigned* hist, unsigned* scan,
                                           int nbins, int tid, int want,
                                           int* s_bin, int* s_wrem) {
    const int chunk = nbins >> 8;
    const int base = tid * chunk;
    unsigned partial = 0;
    #pragma unroll 4
    for (int k = 0; k < chunk; k++) partial += hist[base + k];
    scan[tid] = partial;
    __syncthreads();
    // inclusive suffix sum over 256 chunk-partials
    for (int s = 1; s < 256; s <<= 1) {
        unsigned add = (tid + s < 256) ? scan[tid + s] : 0u;
        __syncthreads();
        scan[tid] += add;
        __syncthreads();
    }
    unsigned running = (tid < 255) ? scan[tid + 1] : 0u;  // count strictly above chunk
    for (int k = chunk - 1; k >= 0; k--) {
        unsigned h = hist[base + k];
        if ((unsigned)want >= running && (unsigned)want < running + h) {
            *s_bin = base + k;
            *s_wrem = (int)((unsigned)want - running);
        }
        running += h;
    }
    __syncthreads();
}

// ---------------- Phase 1: per-box region IoU + exact rank-dk threshold ----------------
__global__ __launch_bounds__(256) void phase1_kernel(
    const float* __restrict__ pred,    // [BS,4,H,W]
    const float* __restrict__ bboxes,  // [BS,NBOX,6]
    const int*   __restrict__ dmode)
{
    extern __shared__ unsigned char dynbuf[];
    float*    vals = (float*)dynbuf;
    unsigned* hist = (unsigned*)(dynbuf + MAXCELLS * 4);
    unsigned* scan = hist + 2048;

    __shared__ float s_wsum[8];
    __shared__ int   s_wcnt[8];
    __shared__ int   s_dk, s_P;
    __shared__ int   s_bin, s_wrem;

    const int bn = blockIdx.x;
    const int b = bn / NBOX;
    const int tid = threadIdx.x;
    const int lane = tid & 31;
    const int wid = tid >> 5;

    const float* bx = bboxes + bn * 6;
    float x1 = bx[0], y1 = bx[1], x2 = bx[2], y2 = bx[3], clsf = bx[4], diff = bx[5];
    float bw = __fsub_rn(x2, x1);
    float bh = __fsub_rn(y2, y1);
    float cx = __fadd_rn(x1, __fmul_rn(bw, 0.5f));
    float cy = __fadd_rn(y1, __fmul_rn(bh, 0.5f));
    bool valid = (__fmul_rn(bw, bh) != 0.0f);

    float mnw = floorf(fmaxf(__fsub_rn(__fdiv_rn(__fmul_rn(x1, (float)WW), MW_F), 0.5f), 0.0f));
    float mnh = floorf(fmaxf(__fsub_rn(__fdiv_rn(__fmul_rn(y1, (float)HH), MH_F), 0.5f), 0.0f));
    float mxw = ceilf (fminf(__fsub_rn(__fdiv_rn(__fmul_rn(x2, (float)WW), MW_F), 0.5f), (float)(WW - 1)));
    float mxh = ceilf (fminf(__fsub_rn(__fdiv_rn(__fmul_rn(y2, (float)HH), MH_F), 0.5f), (float)(HH - 1)));
    int ix0 = (int)mnw, ix1 = (int)mxw, iy0 = (int)mnh, iy1 = (int)mxh;
    bool empty = (!valid) || (ix1 < ix0) || (iy1 < iy0);
    int rw = empty ? 0 : (ix1 - ix0 + 1);
    int rh = empty ? 0 : (iy1 - iy0 + 1);
    int cnt = rw * rh;
    if (cnt > MAXCELLS) cnt = MAXCELLS;

    // zero histogram
    #pragma unroll
    for (int h = tid; h < 2048; h += 256) hist[h] = 0;
    __syncthreads();

    // fused pass: IoU -> vals, sum, positive count, level-1 histogram (bits [31:21])
    float psum = 0.0f;
    int pcount = 0;
    for (int c = tid; c < cnt; c += 256) {
        int ri = c / rw;
        int rj = c - ri * rw;
        int i = iy0 + ri, j = ix0 + rj;
        const float* pb = pred + ((long)b * 4) * HW + (long)i * WW + j;
        float p0 = pb[0 * HW], p1 = pb[1 * HW], p2 = pb[2 * HW], p3 = pb[3 * HW];
        float rx = __fmul_rn(__fadd_rn((float)j, 0.5f), 2.0f);
        float ry = __fmul_rn(__fadd_rn((float)i, 0.5f), 2.0f);
        PGeom g = pred_geom(p0, p1, p2, p3, rx, ry);
        float iou = iou_fn(g, cx, cy, bw, bh);
        vals[c] = iou;
        if (iou > 0.0f) {
            psum += iou;
            pcount++;
            unsigned u = __float_as_uint(iou);
            atomicAdd(&hist[u >> 21], 1u);
        }
    }

    // warp-shuffle reduce sum + positive count
    #pragma unroll
    for (int off = 16; off > 0; off >>= 1) {
        psum += __shfl_down_sync(0xFFFFFFFFu, psum, off);
        pcount += __shfl_down_sync(0xFFFFFFFFu, pcount, off);
    }
    if (lane == 0) { s_wsum[wid] = psum; s_wcnt[wid] = pcount; }
    __syncthreads();
    if (tid == 0) {
        float total = 0.0f; int P = 0;
        #pragma unroll
        for (int w = 0; w < 8; w++) { total += s_wsum[w]; P += s_wcnt[w]; }
        float dkf = ceilf(fmaxf(total, 1.0f));
        if (!(dkf < (float)(HW - 1))) dkf = (float)(HW - 1);
        s_dk = (int)dkf;
        s_P = P;
    }
    __syncthreads();

    const int dk = s_dk;
    const int P = s_P;
    float thr = 0.0f;

    if (dk < P) {
        // level 1: bits [31:21] (already histogrammed)
        locate_bin(hist, scan, 2048, tid, dk, &s_bin, &s_wrem);
        int b1 = s_bin, want2 = s_wrem;
        __syncthreads();

        // level 2: bits [20:10] among values with top bits == b1
        for (int h = tid; h < 2048; h += 256) hist[h] = 0;
        __syncthreads();
        for (int c = tid; c < cnt; c += 256) {
            float v = vals[c];
            if (v > 0.0f) {
                unsigned u = __float_as_uint(v);
                if ((int)(u >> 21) == b1) atomicAdd(&hist[(u >> 10) & 0x7FFu], 1u);
            }
        }
        __syncthreads();
        locate_bin(hist, scan, 2048, tid, want2, &s_bin, &s_wrem);
        int b2 = s_bin, want3 = s_wrem;
        __syncthreads();

        // level 3: bits [9:0] among values with 22-bit prefix == (b1<<11)|b2
        unsigned pref21 = ((unsigned)b1 << 11) | (unsigned)b2;
        for (int h = tid; h < 1024; h += 256) hist[h] = 0;
        __syncthreads();
        for (int c = tid; c < cnt; c += 256) {
            float v = vals[c];
            if (v > 0.0f) {
                unsigned u = __float_as_uint(v);
                if ((u >> 10) == pref21) atomicAdd(&hist[u & 0x3FFu], 1u);
            }
        }
        __syncthreads();
        locate_bin(hist, scan, 1024, tid, want3, &s_bin, &s_wrem);
        int b3 = s_bin;

        unsigned uthr = ((unsigned)b1 << 21) | ((unsigned)b2 << 10) | (unsigned)b3;
        thr = __uint_as_float(uthr);
    }

    if (tid == 0) {
        g_thr[bn] = thr;
        g_cx[bn] = cx; g_cy[bn] = cy; g_bw[bn] = bw; g_bh[bn] = bh;
        int dm = *dmode;
        g_score[bn] = dm ? ((diff >= 0.625f) ? 1.0f : 0.0f) : 1.0f;
        g_lam[bn] = 1.0f / sqrtf((float)dk);
        g_cls[bn] = (int)clsf + 1;
        if (empty) { g_bx[bn] = 0xFFFF; g_by[bn] = 0xFFFF; }
        else       { g_bx[bn] = ix0 | (ix1 << 16); g_by[bn] = iy0 | (iy1 << 16); }
    }
}

// ---------------- Phase 2: per-pixel argmax/tie across boxes + outputs ----------------
__global__ __launch_bounds__(256) void phase2_kernel(
    const float* __restrict__ pred,  // [BS,4,H,W]
    float* __restrict__ out)         // cls [BS,H,W,3] then pts [BS,H,W,6]
{
    __shared__ unsigned s_mask[2];
    __shared__ int   s_ncand;
    __shared__ int   s_bxp[NBOX], s_byp[NBOX], s_clsid[NBOX];
    __shared__ float s_thr[NBOX], s_cx[NBOX], s_cy[NBOX], s_bw[NBOX], s_bh[NBOX];
    __shared__ float s_sc[NBOX], s_lm[NBOX];

    const int b = blockIdx.z;
    const int j0 = blockIdx.x * 64;
    const int i0 = blockIdx.y * 4;
    const int tid = threadIdx.x;

    bool f = false;
    int bxp = 0, byp = 0;
    if (tid < NBOX) {
        int idx = b * NBOX + tid;
        bxp = g_bx[idx]; byp = g_by[idx];
        int x0 = bxp & 0xFFFF, x1 = bxp >> 16;
        int y0 = byp & 0xFFFF, y1 = byp >> 16;
        f = (x0 <= j0 + 63) && (x1 >= j0) && (y0 <= i0 + 3) && (y1 >= i0);
    }
    unsigned m = __ballot_sync(0xFFFFFFFFu, f);
    if (tid < NBOX && (tid & 31) == 0) s_mask[tid >> 5] = m;
    __syncthreads();
    int base0 = __popc(s_mask[0]);
    if (tid == 0) s_ncand = base0 + __popc(s_mask[1]);
    if (f) {
        int lane = tid & 31;
        int pos = ((tid >> 5) ? base0 : 0) + __popc(m & ((1u << lane) - 1u));
        int idx = b * NBOX + tid;
        s_bxp[pos] = bxp; s_byp[pos] = byp;
        s_thr[pos] = g_thr[idx];
        s_cx[pos] = g_cx[idx]; s_cy[pos] = g_cy[idx];
        s_bw[pos] = g_bw[idx]; s_bh[pos] = g_bh[idx];
        s_sc[pos] = g_score[idx]; s_lm[pos] = g_lam[idx];
        s_clsid[pos] = g_cls[idx];
    }
    __syncthreads();

    const int j = j0 + (tid & 63);
    const int i = i0 + (tid >> 6);
    const int pix = i * WW + j;

    const float* pb = pred + ((long)b * 4) * HW + pix;
    float p0 = pb[0 * HW], p1 = pb[1 * HW], p2 = pb[2 * HW], p3 = pb[3 * HW];
    float rx = __fmul_rn(__fadd_rn((float)j, 0.5f), 2.0f);
    float ry = __fmul_rn(__fadd_rn((float)i, 0.5f), 2.0f);
    PGeom g = pred_geom(p0, p1, p2, p3, rx, ry);

    float best = 0.0f;
    int win = 0;
    int cntmax = 0;
    bool inreg = false;
    const int nc = s_ncand;
    for (int k = 0; k < nc; k++) {
        int bp = s_bxp[k], yp = s_byp[k];
        if (j >= (bp & 0xFFFF) && j <= (bp >> 16) &&
            i >= (yp & 0xFFFF) && i <= (yp >> 16)) {
            inreg = true;
            float iou = iou_fn(g, s_cx[k], s_cy[k], s_bw[k], s_bh[k]);
            float kept = (iou > s_thr[k]) ? iou : 0.0f;
            if (kept > best) { best = kept; win = k; cntmax = 1; }
            else if (kept == best && kept > 0.0f) cntmax++;
        }
    }

    bool assigned = (best > 0.0f);
    float c0, c1, c2;
    if (assigned) {
        if (cntmax > 1) { c0 = c1 = c2 = 0.0f; }
        else {
            int ci = s_clsid[win];
            c0 = (ci == 0) ? 1.0f : 0.0f;
            c1 = (ci == 1) ? 1.0f : 0.0f;
            c2 = (ci == 2) ? 1.0f : 0.0f;
        }
    } else if (inreg) {
        c0 = c1 = c2 = 0.0f;
    } else {
        c0 = 1.0f; c1 = 0.0f; c2 = 0.0f;
    }
    int cidx = (b * HW + pix) * 3;
    out[cidx + 0] = c0; out[cidx + 1] = c1; out[cidx + 2] = c2;

    int pidx = BS * HW * 3 + (b * HW + pix) * 6;
    float2* pv = reinterpret_cast<float2*>(out + pidx);  // 8B-aligned: 24B stride + 8B-mult base
    if (assigned) {
        pv[0] = make_float2(s_cx[win], s_cy[win]);
        pv[1] = make_float2(s_bw[win], s_bh[win]);
        pv[2] = make_float2(s_sc[win], s_lm[win]);
    } else {
        pv[0] = make_float2(1.0f, 1.0f);
        pv[1] = make_float2(1.0f, 1.0f);
        pv[2] = make_float2(1.0f, 1.0f);
    }
}

extern "C" void kernel_launch(void* const* d_in, const int* in_sizes, int n_in,
                              void* d_out, int out_size) {
    // inputs: [0]=feat (unused), [1]=pred, [2]=bboxes, [3]=difficult_mode (int32)
    const float* pred   = (const float*)d_in[1];
    const float* bboxes = (const float*)d_in[2];
    const int*   dmode  = (const int*)d_in[3];
    float* out = (float*)d_out;

    cudaFuncSetAttribute(phase1_kernel, cudaFuncAttributeMaxDynamicSharedMemorySize, SMEM1_BYTES);
    phase1_kernel<<<NB, 256, SMEM1_BYTES>>>(pred, bboxes, dmode);
    dim3 g2(WW / 64, HH / 4, BS);
    phase2_kernel<<<g2, 256>>>(pred, out);
}